// round 9
// baseline (speedup 1.0000x reference)
#include <cuda_runtime.h>
#include <cstdint>

// Problem constants (fixed shape instance)
constexpr int B = 64;
constexpr int Q = 1024;
constexpr int N = 2048;
constexpr int C = 2048;
constexpr int P = 512;
constexpr int W = 256;
constexpr int HALF = W / 2;

// GEMM tiling: block tile 64b x 64j x 32k; grid = 8 j-tiles x 64 k-splits = 512
constexpr int KC  = 32;
constexpr int KS  = C / KC;   // 64
constexpr int JT  = 64;
constexpr int NJT = P / JT;   // 8
constexpr int RST = 36;       // smem row stride (floats) = 9 x 16B chunks (odd -> conflict-free)

// Scratch (__device__ globals: allocation-free rule)
__device__ float d_Hpart[KS * B * P];   // 8 MB split partials (L2-resident)
__device__ float d_partial[B * NJT];    // per-(b, j-tile) v_p.tanh partial dots

// ---------------------------------------------------------------------------
// K1: Hpart[ks][b][j] = sum_{k in chunk ks} c_t[b,k] * w_p[j,k]
// grid 512 (jt = bid&7, ks = bid>>3), 128 threads.
// Pure C++ scalar FMA (ptxas schedules freely), float4 smem ops, zero asm.
// Thread (bg = t&15, jg = t>>4): b in {bg+16i}, j in {8*jg .. 8*jg+7}.
// ---------------------------------------------------------------------------
__global__ __launch_bounds__(128) void gemm_kernel(
    const float* __restrict__ c_t, const float* __restrict__ w_p)
{
    __shared__ float sc[B][RST];    // [b][k] row-major, KC=32 floats + pad
    __shared__ float sw[JT][RST];   // [j][k] row-major

    const int jt = blockIdx.x & (NJT - 1);
    const int ks = blockIdx.x >> 3;
    const int k0 = ks * KC;
    const int t  = threadIdx.x;

    // Fill tiles: straight float4 LDG -> float4 STS (no transpose).
#pragma unroll
    for (int r = 0; r < 4; r++) {
        int idx = t + 128 * r;          // 0..511
        int row = idx >> 3, ch = idx & 7;
        float4 cv = *reinterpret_cast<const float4*>(c_t + (size_t)row * C + k0 + ch * 4);
        *reinterpret_cast<float4*>(&sc[row][ch * 4]) = cv;
        float4 wv = *reinterpret_cast<const float4*>(w_p + (size_t)(jt * JT + row) * C + k0 + ch * 4);
        *reinterpret_cast<float4*>(&sw[row][ch * 4]) = wv;
    }
    __syncthreads();

    const int bg = t & 15;
    const int jg = t >> 4;          // 0..7, j row base = 8*jg

    float acc[4][8];
#pragma unroll
    for (int i = 0; i < 4; i++)
#pragma unroll
        for (int jj = 0; jj < 8; jj++) acc[i][jj] = 0.f;

#pragma unroll
    for (int kc = 0; kc < KC / 4; kc++) {
        float4 cv[4];
#pragma unroll
        for (int i = 0; i < 4; i++)
            cv[i] = *reinterpret_cast<const float4*>(&sc[bg + 16 * i][kc * 4]);
#pragma unroll
        for (int jj = 0; jj < 8; jj++) {
            float4 wv = *reinterpret_cast<const float4*>(&sw[8 * jg + jj][kc * 4]);
#pragma unroll
            for (int i = 0; i < 4; i++) {
                acc[i][jj] = fmaf(cv[i].x, wv.x, acc[i][jj]);
                acc[i][jj] = fmaf(cv[i].y, wv.y, acc[i][jj]);
                acc[i][jj] = fmaf(cv[i].z, wv.z, acc[i][jj]);
                acc[i][jj] = fmaf(cv[i].w, wv.w, acc[i][jj]);
            }
        }
    }

    // Epilogue: two float4 stores per b-row (j contiguous).
#pragma unroll
    for (int i = 0; i < 4; i++) {
        int b = bg + 16 * i;
        size_t row = ((size_t)ks * B + b) * P + jt * JT + 8 * jg;
        *reinterpret_cast<float4*>(&d_Hpart[row]) =
            make_float4(acc[i][0], acc[i][1], acc[i][2], acc[i][3]);
        *reinterpret_cast<float4*>(&d_Hpart[row + 4]) =
            make_float4(acc[i][4], acc[i][5], acc[i][6], acc[i][7]);
    }
}

// ---------------------------------------------------------------------------
// K2: per (b, j-tile): Hsum = sum_ks Hpart; partial[b][jt] = sum_j v_p.tanh(Hsum)
// grid 512 (b = bid>>3, jt = bid&7), 256 thr.
// ---------------------------------------------------------------------------
__global__ __launch_bounds__(256) void reduce_head_kernel(
    const float* __restrict__ v_p)
{
    const int b  = blockIdx.x >> 3;
    const int jt = blockIdx.x & 7;
    const int t  = threadIdx.x;
    const int jq = t & 15;           // j-quad within 64-j tile
    const int g  = t >> 4;           // 0..15 ks-group

    float4 s = make_float4(0.f, 0.f, 0.f, 0.f);
#pragma unroll
    for (int i = 0; i < 4; i++) {
        int ks = g + 16 * i;
        float4 h = *reinterpret_cast<const float4*>(
            &d_Hpart[((size_t)ks * B + b) * P + jt * JT + jq * 4]);
        s.x += h.x; s.y += h.y; s.z += h.z; s.w += h.w;
    }
    __shared__ float4 hs[16][16];
    hs[g][jq] = s;
    __syncthreads();

    __shared__ float red[2];
    if (t < 64) {
        int quad = t >> 2, c = t & 3;
        float sum = 0.f;
#pragma unroll
        for (int g2 = 0; g2 < 16; g2++)
            sum += reinterpret_cast<const float*>(&hs[g2][quad])[c];
        float part = __ldg(v_p + jt * JT + t) * tanhf(sum);
#pragma unroll
        for (int o = 16; o > 0; o >>= 1)
            part += __shfl_down_sync(0xffffffffu, part, o);
        if ((t & 31) == 0) red[t >> 5] = part;
    }
    __syncthreads();
    if (t == 0) d_partial[b * NJT + jt] = red[0] + red[1];
}

// ---------------------------------------------------------------------------
// K4: head recompute (from 8 partials) + window sum with aligned float4 loads.
// s_t[b,q] = sum_w g[b,w] * q_i[b, q, base + w]
// grid (8, 64), 256 thr, 128 rows per block.
// ---------------------------------------------------------------------------
constexpr int GWN = 272;   // aligned weight span: 68 float4

__global__ __launch_bounds__(256) void window_sum_kernel(
    const float* __restrict__ q_i, float* __restrict__ out)
{
    __shared__ float s_gw[GWN];
    __shared__ float s_pt;
    __shared__ int   s_base, s_ba;

    const int b  = blockIdx.y;
    const int q0 = blockIdx.x * 128;
    const int t  = threadIdx.x;

    if (t == 0) {
        float x = 0.f;
#pragma unroll
        for (int i = 0; i < NJT; i++) x += d_partial[b * NJT + i];
        float loc = 1.f / (1.f + expf(-x));
        float pt  = loc * (float)(N - 1);      // loc * 2047
        int   p   = (int)rintf(pt);            // round-half-even == jnp.round
        int base = p - HALF;
        if (base < 0) base = 0;
        if (base > N - W) base = N - W;
        int ba = base & ~3;                    // float4-aligned read start
        if (ba > N - GWN) ba = N - GWN;
        s_pt = pt; s_base = base; s_ba = ba;
    }
    __syncthreads();

    const float pt  = s_pt;
    const int base  = s_base;
    const int ba    = s_ba;

    if (t < GWN - 256) {   // entries 256..271
        int j = 256 + t;
        int n = ba + j;
        float w = 0.f;
        if (n >= base && n < base + W) {
            float d = ((float)n - pt) * (1.0f / (float)HALF);
            w = expf(-2.f * d * d);
        }
        s_gw[j] = w;
    }
    {
        int n = ba + t;
        float w = 0.f;
        if (n >= base && n < base + W) {
            float d = ((float)n - pt) * (1.0f / (float)HALF);
            w = expf(-2.f * d * d);
        }
        s_gw[t] = w;
    }
    __syncthreads();

    const int warp = t >> 5, lane = t & 31;

    float4 g0 = *reinterpret_cast<const float4*>(&s_gw[8 * lane]);
    float4 g1 = *reinterpret_cast<const float4*>(&s_gw[8 * lane + 4]);
    float4 gx = make_float4(0.f, 0.f, 0.f, 0.f);
    if (lane < 4) gx = *reinterpret_cast<const float4*>(&s_gw[256 + 4 * lane]);

    const float* rowbase = q_i + ((size_t)b * Q + q0 + warp * 16) * N + ba;
    float* outbase = out + (size_t)b * Q + q0 + warp * 16;

#pragma unroll 2
    for (int r = 0; r < 16; r += 2) {
        const float4* r0 = reinterpret_cast<const float4*>(rowbase + (size_t)r * N);
        const float4* r1 = reinterpret_cast<const float4*>(rowbase + (size_t)(r + 1) * N);

        float4 a0 = __ldg(r0 + 2 * lane);
        float4 a1 = __ldg(r0 + 2 * lane + 1);
        float4 b0 = __ldg(r1 + 2 * lane);
        float4 b1 = __ldg(r1 + 2 * lane + 1);
        float4 ax = make_float4(0.f, 0.f, 0.f, 0.f);
        float4 bx = ax;
        if (lane < 4) { ax = __ldg(r0 + 64 + lane); bx = __ldg(r1 + 64 + lane); }

        float acc0 = a0.x * g0.x + a0.y * g0.y + a0.z * g0.z + a0.w * g0.w
                   + a1.x * g1.x + a1.y * g1.y + a1.z * g1.z + a1.w * g1.w
                   + ax.x * gx.x + ax.y * gx.y + ax.z * gx.z + ax.w * gx.w;
        float acc1 = b0.x * g0.x + b0.y * g0.y + b0.z * g0.z + b0.w * g0.w
                   + b1.x * g1.x + b1.y * g1.y + b1.z * g1.z + b1.w * g1.w
                   + bx.x * gx.x + bx.y * gx.y + bx.z * gx.z + bx.w * gx.w;

#pragma unroll
        for (int o = 16; o > 0; o >>= 1) {
            acc0 += __shfl_down_sync(0xffffffffu, acc0, o);
            acc1 += __shfl_down_sync(0xffffffffu, acc1, o);
        }
        if (lane == 0) { outbase[r] = acc0; outbase[r + 1] = acc1; }
    }
}

// ---------------------------------------------------------------------------
extern "C" void kernel_launch(void* const* d_in, const int* in_sizes, int n_in,
                              void* d_out, int out_size)
{
    const float* q_i = (const float*)d_in[0];  // (B,Q,N)
    const float* c_t = (const float*)d_in[1];  // (B,C)
    // d_in[2] = w_a : cancels (softmax over singleton axis == 1)
    const float* w_p = (const float*)d_in[3];  // (P,C)
    const float* v_p = (const float*)d_in[4];  // (1,P)
    float* out = (float*)d_out;                // (B,Q)

    gemm_kernel<<<NJT * KS, 128>>>(c_t, w_p);
    reduce_head_kernel<<<B * NJT, 256>>>(v_p);
    window_sum_kernel<<<dim3(Q / 128, B), 256>>>(q_i, out);
}

// round 10
// speedup vs baseline: 1.1321x; 1.1321x over previous
#include <cuda_runtime.h>
#include <cstdint>

// Problem constants (fixed shape instance)
constexpr int B = 64;
constexpr int Q = 1024;
constexpr int N = 2048;
constexpr int C = 2048;
constexpr int P = 512;
constexpr int W = 256;
constexpr int HALF = W / 2;

// GEMM tiling (R3 config — best measured): 64b x 64j x 64k, grid (8, 32)
constexpr int KC  = 64;
constexpr int KS  = C / KC;   // 32
constexpr int JT  = 64;
constexpr int NJT = P / JT;   // 8
constexpr int SST = 68;       // smem row stride (floats): conflict-free, 16B-aligned

// Scratch (__device__ globals: allocation-free rule)
__device__ float d_Hpart[KS * B * P];   // 4 MB split partials (L2-resident)
__device__ float d_partial[B * NJT];    // per-(b, j-tile) v_p.tanh partial dots

__device__ __forceinline__ unsigned long long pk2(float lo, float hi) {
    unsigned long long r;
    asm("mov.b64 %0, {%1, %2};" : "=l"(r) : "f"(lo), "f"(hi));
    return r;
}
__device__ __forceinline__ void fma2(unsigned long long& d,
                                     unsigned long long a, unsigned long long b) {
    asm("fma.rn.f32x2 %0, %1, %2, %0;" : "+l"(d) : "l"(a), "l"(b));
}

// ---------------------------------------------------------------------------
// K1 (R3 GEMM, unchanged): Hpart[ks][b][j] = sum_{k in chunk} c_t[b,k]*w_p[j,k]
// grid (NJT, KS), 256 threads. Thread tile 4b x 4j, f32x2 over j-pairs.
// ---------------------------------------------------------------------------
__global__ __launch_bounds__(256, 4) void gemm_kernel(
    const float* __restrict__ c_t, const float* __restrict__ w_p)
{
    __shared__ float sc[KC][SST];   // k-major c tile: 64k x 64b
    __shared__ float sw[KC][SST];   // k-major w tile: 64k x 64j

    const int jt = blockIdx.x;
    const int ks = blockIdx.y;
    const int k0 = ks * KC;
    const int t  = threadIdx.x;
    const int kl  = t & 63;
    const int grp = t >> 6;          // 0..3

#pragma unroll
    for (int it = 0; it < 4; it++) {
        int bq = grp * 4 + it;       // 0..15
        const float* cr = c_t + (size_t)(bq * 4) * C + k0 + kl;
        float v0 = __ldg(cr);
        float v1 = __ldg(cr + C);
        float v2 = __ldg(cr + 2 * C);
        float v3 = __ldg(cr + 3 * C);
        *reinterpret_cast<float4*>(&sc[kl][bq * 4]) = make_float4(v0, v1, v2, v3);
    }
#pragma unroll
    for (int it = 0; it < 4; it++) {
        int jq = grp * 4 + it;       // 0..15
        const float* wr = w_p + (size_t)(jt * JT + jq * 4) * C + k0 + kl;
        float v0 = __ldg(wr);
        float v1 = __ldg(wr + C);
        float v2 = __ldg(wr + 2 * C);
        float v3 = __ldg(wr + 3 * C);
        *reinterpret_cast<float4*>(&sw[kl][jq * 4]) = make_float4(v0, v1, v2, v3);
    }
    __syncthreads();

    const int jg = t & 15;
    const int bg = t >> 4;
    const int b0 = bg * 4;
    const int j0 = jg * 4;

    unsigned long long acc[4][2];    // [bb][j-pair]
#pragma unroll
    for (int bb = 0; bb < 4; bb++) { acc[bb][0] = 0ull; acc[bb][1] = 0ull; }

#pragma unroll 8
    for (int k = 0; k < KC; k++) {
        float4 ca = *reinterpret_cast<const float4*>(&sc[k][b0]);
        ulonglong2 wv = *reinterpret_cast<const ulonglong2*>(&sw[k][j0]);
        unsigned long long cd0 = pk2(ca.x, ca.x);
        unsigned long long cd1 = pk2(ca.y, ca.y);
        unsigned long long cd2 = pk2(ca.z, ca.z);
        unsigned long long cd3 = pk2(ca.w, ca.w);
        fma2(acc[0][0], cd0, wv.x); fma2(acc[0][1], cd0, wv.y);
        fma2(acc[1][0], cd1, wv.x); fma2(acc[1][1], cd1, wv.y);
        fma2(acc[2][0], cd2, wv.x); fma2(acc[2][1], cd2, wv.y);
        fma2(acc[3][0], cd3, wv.x); fma2(acc[3][1], cd3, wv.y);
    }

#pragma unroll
    for (int bb = 0; bb < 4; bb++) {
        size_t row = ((size_t)ks * B + (b0 + bb)) * P + jt * JT + j0;
        *reinterpret_cast<ulonglong2*>(&d_Hpart[row]) =
            make_ulonglong2(acc[bb][0], acc[bb][1]);
    }
}

// ---------------------------------------------------------------------------
// K2: per (b, j-tile): Hsum = sum_ks Hpart; partial[b][jt] = sum_j v_p.tanh
// grid 512 (b = bid>>3, jt = bid&7), 256 thr. KS=32: 2 splits per thread.
// ---------------------------------------------------------------------------
__global__ __launch_bounds__(256) void reduce_head_kernel(
    const float* __restrict__ v_p)
{
    const int b  = blockIdx.x >> 3;
    const int jt = blockIdx.x & 7;
    const int t  = threadIdx.x;
    const int jq = t & 15;           // j-quad within 64-j tile
    const int g  = t >> 4;           // 0..15 ks-group

    float4 s = make_float4(0.f, 0.f, 0.f, 0.f);
#pragma unroll
    for (int i = 0; i < 2; i++) {
        int ks = g + 16 * i;
        float4 h = *reinterpret_cast<const float4*>(
            &d_Hpart[((size_t)ks * B + b) * P + jt * JT + jq * 4]);
        s.x += h.x; s.y += h.y; s.z += h.z; s.w += h.w;
    }
    __shared__ float4 hs[16][16];
    hs[g][jq] = s;
    __syncthreads();

    __shared__ float red[2];
    if (t < 64) {
        int quad = t >> 2, c = t & 3;
        float sum = 0.f;
#pragma unroll
        for (int g2 = 0; g2 < 16; g2++)
            sum += reinterpret_cast<const float*>(&hs[g2][quad])[c];
        float part = __ldg(v_p + jt * JT + t) * tanhf(sum);
#pragma unroll
        for (int o = 16; o > 0; o >>= 1)
            part += __shfl_down_sync(0xffffffffu, part, o);
        if ((t & 31) == 0) red[t >> 5] = part;
    }
    __syncthreads();
    if (t == 0) d_partial[b * NJT + jt] = red[0] + red[1];
}

// ---------------------------------------------------------------------------
// K3 (R3-style window, + fused head recompute): one warp per q row.
// s_t[b,q] = sum_w g[b,w] * q_i[b, q, base + w]
// grid (Q/8 = 128, B), 256 thr -> 8192 blocks, 65536 row-warps (max MLP).
// ---------------------------------------------------------------------------
__global__ __launch_bounds__(256) void window_sum_kernel(
    const float* __restrict__ q_i, float* __restrict__ out)
{
    __shared__ float g[W];
    __shared__ float s_pt;
    __shared__ int   s_base;

    const int b = blockIdx.y;
    const int t = threadIdx.x;

    // head recompute (deterministic, identical for all blocks of batch b)
    if (t == 0) {
        float x = 0.f;
#pragma unroll
        for (int i = 0; i < NJT; i++) x += d_partial[b * NJT + i];
        float loc = 1.f / (1.f + expf(-x));
        float pt  = loc * (float)(N - 1);      // loc * 2047
        int   p   = (int)rintf(pt);            // round-half-even == jnp.round
        int base = p - HALF;
        if (base < 0) base = 0;
        if (base > N - W) base = N - W;
        s_pt = pt; s_base = base;
    }
    __syncthreads();

    {   // gaussian weights (blockDim == W)
        int n = s_base + t;
        float d = ((float)n - s_pt) * (1.0f / (float)HALF);
        g[t] = expf(-2.f * d * d);
    }
    __syncthreads();

    const int warp = t >> 5, lane = t & 31;
    const int q = blockIdx.x * 8 + warp;
    const float* row = q_i + ((size_t)b * Q + q) * N + s_base;

    float x[8];
#pragma unroll
    for (int i = 0; i < 8; i++) x[i] = __ldg(row + lane + 32 * i);
    float acc = 0.f;
#pragma unroll
    for (int i = 0; i < 8; i++) acc += g[lane + 32 * i] * x[i];

#pragma unroll
    for (int o = 16; o > 0; o >>= 1)
        acc += __shfl_down_sync(0xffffffffu, acc, o);

    if (lane == 0) out[(size_t)b * Q + q] = acc;
}

// ---------------------------------------------------------------------------
extern "C" void kernel_launch(void* const* d_in, const int* in_sizes, int n_in,
                              void* d_out, int out_size)
{
    const float* q_i = (const float*)d_in[0];  // (B,Q,N)
    const float* c_t = (const float*)d_in[1];  // (B,C)
    // d_in[2] = w_a : cancels (softmax over singleton axis == 1)
    const float* w_p = (const float*)d_in[3];  // (P,C)
    const float* v_p = (const float*)d_in[4];  // (1,P)
    float* out = (float*)d_out;                // (B,Q)

    gemm_kernel<<<dim3(NJT, KS), 256>>>(c_t, w_p);
    reduce_head_kernel<<<B * NJT, 256>>>(v_p);
    window_sum_kernel<<<dim3(Q / 8, B), 256>>>(q_i, out);
}

// round 11
// speedup vs baseline: 1.3064x; 1.1540x over previous
#include <cuda_runtime.h>
#include <cstdint>

// Problem constants (fixed shape instance)
constexpr int B = 64;
constexpr int Q = 1024;
constexpr int N = 2048;
constexpr int C = 2048;
constexpr int P = 512;
constexpr int W = 256;
constexpr int HALF = W / 2;

// GEMM tiling (best measured): 64b x 64j x 64k, grid (8, 32)
constexpr int KC  = 64;
constexpr int KS  = C / KC;   // 32
constexpr int JT  = 64;
constexpr int NJT = P / JT;   // 8
constexpr int SST = 68;       // smem row stride (floats): conflict-free, 16B-aligned

// Scratch (__device__ globals: allocation-free rule)
__device__ float d_Hpart[KS * B * P];   // 4 MB split partials (L2-resident)
__device__ float d_partial[B * NJT];    // per-(b, j-tile) v_p.tanh partial dots

__device__ __forceinline__ unsigned long long pk2(float lo, float hi) {
    unsigned long long r;
    asm("mov.b64 %0, {%1, %2};" : "=l"(r) : "f"(lo), "f"(hi));
    return r;
}
__device__ __forceinline__ void fma2(unsigned long long& d,
                                     unsigned long long a, unsigned long long b) {
    asm("fma.rn.f32x2 %0, %1, %2, %0;" : "+l"(d) : "l"(a), "l"(b));
}

// ---------------------------------------------------------------------------
// K1 (unchanged, 8.38us measured): Hpart[ks][b][j] = sum_k c_t[b,k]*w_p[j,k]
// grid (NJT, KS), 256 threads. Thread tile 4b x 4j, f32x2 over j-pairs.
// ---------------------------------------------------------------------------
__global__ __launch_bounds__(256, 4) void gemm_kernel(
    const float* __restrict__ c_t, const float* __restrict__ w_p)
{
    __shared__ float sc[KC][SST];   // k-major c tile: 64k x 64b
    __shared__ float sw[KC][SST];   // k-major w tile: 64k x 64j

    const int jt = blockIdx.x;
    const int ks = blockIdx.y;
    const int k0 = ks * KC;
    const int t  = threadIdx.x;
    const int kl  = t & 63;
    const int grp = t >> 6;          // 0..3

#pragma unroll
    for (int it = 0; it < 4; it++) {
        int bq = grp * 4 + it;       // 0..15
        const float* cr = c_t + (size_t)(bq * 4) * C + k0 + kl;
        float v0 = __ldg(cr);
        float v1 = __ldg(cr + C);
        float v2 = __ldg(cr + 2 * C);
        float v3 = __ldg(cr + 3 * C);
        *reinterpret_cast<float4*>(&sc[kl][bq * 4]) = make_float4(v0, v1, v2, v3);
    }
#pragma unroll
    for (int it = 0; it < 4; it++) {
        int jq = grp * 4 + it;       // 0..15
        const float* wr = w_p + (size_t)(jt * JT + jq * 4) * C + k0 + kl;
        float v0 = __ldg(wr);
        float v1 = __ldg(wr + C);
        float v2 = __ldg(wr + 2 * C);
        float v3 = __ldg(wr + 3 * C);
        *reinterpret_cast<float4*>(&sw[kl][jq * 4]) = make_float4(v0, v1, v2, v3);
    }
    __syncthreads();

    const int jg = t & 15;
    const int bg = t >> 4;
    const int b0 = bg * 4;
    const int j0 = jg * 4;

    unsigned long long acc[4][2];    // [bb][j-pair]
#pragma unroll
    for (int bb = 0; bb < 4; bb++) { acc[bb][0] = 0ull; acc[bb][1] = 0ull; }

#pragma unroll 8
    for (int k = 0; k < KC; k++) {
        float4 ca = *reinterpret_cast<const float4*>(&sc[k][b0]);
        ulonglong2 wv = *reinterpret_cast<const ulonglong2*>(&sw[k][j0]);
        unsigned long long cd0 = pk2(ca.x, ca.x);
        unsigned long long cd1 = pk2(ca.y, ca.y);
        unsigned long long cd2 = pk2(ca.z, ca.z);
        unsigned long long cd3 = pk2(ca.w, ca.w);
        fma2(acc[0][0], cd0, wv.x); fma2(acc[0][1], cd0, wv.y);
        fma2(acc[1][0], cd1, wv.x); fma2(acc[1][1], cd1, wv.y);
        fma2(acc[2][0], cd2, wv.x); fma2(acc[2][1], cd2, wv.y);
        fma2(acc[3][0], cd3, wv.x); fma2(acc[3][1], cd3, wv.y);
    }

#pragma unroll
    for (int bb = 0; bb < 4; bb++) {
        size_t row = ((size_t)ks * B + (b0 + bb)) * P + jt * JT + j0;
        *reinterpret_cast<ulonglong2*>(&d_Hpart[row]) =
            make_ulonglong2(acc[bb][0], acc[bb][1]);
    }
}

// ---------------------------------------------------------------------------
// K2 (unchanged): per (b, j-tile): Hsum = sum_ks Hpart; partial = v_p.tanh dot
// grid 512 (b = bid>>3, jt = bid&7), 256 thr.
// ---------------------------------------------------------------------------
__global__ __launch_bounds__(256) void reduce_head_kernel(
    const float* __restrict__ v_p)
{
    const int b  = blockIdx.x >> 3;
    const int jt = blockIdx.x & 7;
    const int t  = threadIdx.x;
    const int jq = t & 15;           // j-quad within 64-j tile
    const int g  = t >> 4;           // 0..15 ks-group

    float4 s = make_float4(0.f, 0.f, 0.f, 0.f);
#pragma unroll
    for (int i = 0; i < 2; i++) {
        int ks = g + 16 * i;
        float4 h = *reinterpret_cast<const float4*>(
            &d_Hpart[((size_t)ks * B + b) * P + jt * JT + jq * 4]);
        s.x += h.x; s.y += h.y; s.z += h.z; s.w += h.w;
    }
    __shared__ float4 hs[16][16];
    hs[g][jq] = s;
    __syncthreads();

    __shared__ float red[2];
    if (t < 64) {
        int quad = t >> 2, c = t & 3;
        float sum = 0.f;
#pragma unroll
        for (int g2 = 0; g2 < 16; g2++)
            sum += reinterpret_cast<const float*>(&hs[g2][quad])[c];
        float part = __ldg(v_p + jt * JT + t) * tanhf(sum);
#pragma unroll
        for (int o = 16; o > 0; o >>= 1)
            part += __shfl_down_sync(0xffffffffu, part, o);
        if ((t & 31) == 0) red[t >> 5] = part;
    }
    __syncthreads();
    if (t == 0) d_partial[b * NJT + jt] = red[0] + red[1];
}

// ---------------------------------------------------------------------------
// K3 v2: window sum, 2 rows per warp, __ldcs streaming loads.
// s_t[b,q] = sum_w g[b,w] * q_i[b, q, base + w]
// grid (Q/16 = 64, B) = 4096 blocks, 256 thr (8 warps x 2 rows).
// ---------------------------------------------------------------------------
__global__ __launch_bounds__(256) void window_sum_kernel(
    const float* __restrict__ q_i, float* __restrict__ out)
{
    __shared__ float g[W];
    __shared__ float s_pt;
    __shared__ int   s_base;

    const int b = blockIdx.y;
    const int t = threadIdx.x;

    // head recompute (deterministic, identical for all blocks of batch b)
    if (t == 0) {
        float x = 0.f;
#pragma unroll
        for (int i = 0; i < NJT; i++) x += d_partial[b * NJT + i];
        float loc = 1.f / (1.f + expf(-x));
        float pt  = loc * (float)(N - 1);      // loc * 2047
        int   p   = (int)rintf(pt);            // round-half-even == jnp.round
        int base = p - HALF;
        if (base < 0) base = 0;
        if (base > N - W) base = N - W;
        s_pt = pt; s_base = base;
    }
    __syncthreads();

    {   // gaussian weights (blockDim == W)
        int n = s_base + t;
        float d = ((float)n - s_pt) * (1.0f / (float)HALF);
        g[t] = expf(-2.f * d * d);
    }
    __syncthreads();

    const int warp = t >> 5, lane = t & 31;
    const int q = blockIdx.x * 16 + warp * 2;
    const float* row0 = q_i + ((size_t)b * Q + q) * N + s_base;
    const float* row1 = row0 + N;

    float gw[8];
#pragma unroll
    for (int i = 0; i < 8; i++) gw[i] = g[lane + 32 * i];

    float x0[8], x1[8];
#pragma unroll
    for (int i = 0; i < 8; i++) x0[i] = __ldcs(row0 + lane + 32 * i);
#pragma unroll
    for (int i = 0; i < 8; i++) x1[i] = __ldcs(row1 + lane + 32 * i);

    float a0 = 0.f, a1 = 0.f;
#pragma unroll
    for (int i = 0; i < 8; i++) { a0 += gw[i] * x0[i]; a1 += gw[i] * x1[i]; }

#pragma unroll
    for (int o = 16; o > 0; o >>= 1) {
        a0 += __shfl_down_sync(0xffffffffu, a0, o);
        a1 += __shfl_down_sync(0xffffffffu, a1, o);
    }
    if (lane == 0) {
        out[(size_t)b * Q + q]     = a0;
        out[(size_t)b * Q + q + 1] = a1;
    }
}

// ---------------------------------------------------------------------------
extern "C" void kernel_launch(void* const* d_in, const int* in_sizes, int n_in,
                              void* d_out, int out_size)
{
    const float* q_i = (const float*)d_in[0];  // (B,Q,N)
    const float* c_t = (const float*)d_in[1];  // (B,C)
    // d_in[2] = w_a : cancels (softmax over singleton axis == 1)
    const float* w_p = (const float*)d_in[3];  // (P,C)
    const float* v_p = (const float*)d_in[4];  // (1,P)
    float* out = (float*)d_out;                // (B,Q)

    gemm_kernel<<<dim3(NJT, KS), 256>>>(c_t, w_p);
    reduce_head_kernel<<<B * NJT, 256>>>(v_p);
    window_sum_kernel<<<dim3(Q / 16, B), 256>>>(q_i, out);
}